// round 2
// baseline (speedup 1.0000x reference)
#include <cuda_runtime.h>
#include <cuda_bf16.h>
#include <cstdint>

// Problem constants
#define BB 4
#define TT 2048
#define DD 1024
#define HH 16
#define DKK 64
#define DVV 128
#define KK (HH*DKK)   // 1024
#define VV (HH*DVV)   // 2048
#define MM (BB*TT)    // 8192

// ---------------- scratch (device globals; no allocation) ----------------
__device__ float g_r [MM*KK];
__device__ float g_k [MM*KK];
__device__ float g_w [MM*KK];
__device__ float g_xw[MM*DD];
__device__ float g_v [MM*VV];
__device__ float g_g [MM*VV];
__device__ float g_o [MM*VV];
__device__ float g_h1[MM*32];
__device__ float g_h2[MM*32];

// ---------------- GEMM: C[M,N] = f( Aload(A)[M,Kd] @ B[Kd,N] ) ----------------
// AMODE: 0 = plain A; 1 = token-shift modulated: a = x + (x_prev - x)*mu[k]
// EPI:   0 = store acc
//        1 = tanh(acc)
//        2 = xw-combine: C = X + (X_prev - X) * (acc + bias[n])
//        3 = -exp(acc + bias[n])
#define GBM 128
#define GBN 128
#define GBK 8

template<int AMODE, int EPI>
__global__ __launch_bounds__(256)
void gemm_kernel(const float* __restrict__ A, const float* __restrict__ B,
                 float* __restrict__ C, int M, int N, int Kd,
                 const float* __restrict__ mu, const float* __restrict__ bias,
                 const float* __restrict__ X)
{
    __shared__ float As[GBK][GBM];
    __shared__ float Bs[GBK][GBN + 4];

    const int tid = threadIdx.x;           // 256 threads
    const int tx = tid & 15;               // 0..15
    const int ty = tid >> 4;               // 0..15

    const int rowA = tid >> 1;             // 0..127
    const int colA = (tid & 1) * 4;        // 0 or 4
    const int rowB = tid >> 5;             // 0..7
    const int colB = (tid & 31) * 4;       // 0..124

    const int gRowA = blockIdx.y * GBM + rowA;   // M is multiple of 128
    const bool isT0 = ((gRowA & (TT - 1)) == 0); // first token of a batch row

    float acc[8][8];
#pragma unroll
    for (int i = 0; i < 8; i++)
#pragma unroll
        for (int j = 0; j < 8; j++) acc[i][j] = 0.f;

    const int gnB = blockIdx.x * GBN + colB;

    for (int k0 = 0; k0 < Kd; k0 += GBK) {
        // ---- load A tile (optionally token-shift modulated) ----
        const float* aptr = A + (size_t)gRowA * Kd + (k0 + colA);
        float4 a = *(const float4*)aptr;
        if (AMODE == 1) {
            float4 p;
            if (isT0) { p.x = p.y = p.z = p.w = 0.f; }
            else      { p = *(const float4*)(aptr - Kd); }
            float4 m4 = *(const float4*)(mu + k0 + colA);
            a.x = a.x + (p.x - a.x) * m4.x;
            a.y = a.y + (p.y - a.y) * m4.y;
            a.z = a.z + (p.z - a.z) * m4.z;
            a.w = a.w + (p.w - a.w) * m4.w;
        }
        As[colA + 0][rowA] = a.x;
        As[colA + 1][rowA] = a.y;
        As[colA + 2][rowA] = a.z;
        As[colA + 3][rowA] = a.w;

        // ---- load B tile (guard N for N=32 cases) ----
        float4 b;
        if (gnB < N) b = *(const float4*)(B + (size_t)(k0 + rowB) * N + gnB);
        else { b.x = b.y = b.z = b.w = 0.f; }
        *(float4*)&Bs[rowB][colB] = b;

        __syncthreads();

#pragma unroll
        for (int kk = 0; kk < GBK; ++kk) {
            float ra[8], rb[8];
            *(float4*)&ra[0] = *(const float4*)&As[kk][ty * 8];
            *(float4*)&ra[4] = *(const float4*)&As[kk][ty * 8 + 4];
            *(float4*)&rb[0] = *(const float4*)&Bs[kk][tx * 8];
            *(float4*)&rb[4] = *(const float4*)&Bs[kk][tx * 8 + 4];
#pragma unroll
            for (int i = 0; i < 8; i++)
#pragma unroll
                for (int j = 0; j < 8; j++)
                    acc[i][j] += ra[i] * rb[j];
        }
        __syncthreads();
    }

    // ---- epilogue ----
#pragma unroll
    for (int i = 0; i < 8; i++) {
        const int row = blockIdx.y * GBM + ty * 8 + i;
        const bool rT0 = ((row & (TT - 1)) == 0);
#pragma unroll
        for (int j = 0; j < 8; j++) {
            const int col = blockIdx.x * GBN + tx * 8 + j;
            if (col >= N) continue;
            const size_t cidx = (size_t)row * N + col;
            float vacc = acc[i][j];
            if (EPI == 0) {
                C[cidx] = vacc;
            } else if (EPI == 1) {
                C[cidx] = tanhf(vacc);
            } else if (EPI == 2) {
                float lam = vacc + bias[col];
                float xv = X[cidx];
                float xp = rT0 ? 0.f : X[cidx - N];
                C[cidx] = xv + (xp - xv) * lam;
            } else if (EPI == 3) {
                C[cidx] = -expf(vacc + bias[col]);
            }
        }
    }
}

// ---------------- recurrent scan ----------------
// grid = B*H CTAs; 256 threads: (half = tid/128) in {0,1} covers k in [half*32, half*32+32),
// vv = tid%128 covers DV. State h[32] per thread in registers.
__global__ __launch_bounds__(256)
void scan_kernel(const float* __restrict__ r, const float* __restrict__ k,
                 const float* __restrict__ v, const float* __restrict__ w,
                 const float* __restrict__ bonus, float* __restrict__ o)
{
    const int bh = blockIdx.x;
    const int b = bh / HH;
    const int hh = bh % HH;
    const int tid = threadIdx.x;
    const int vv = tid & 127;
    const int half = tid >> 7;
    const int kbase = half * 32;

    __shared__ float s_r[DKK], s_k[DKK], s_uk[DKK], s_ew[DKK];
    __shared__ float s_v[DVV], s_part[DVV];
    __shared__ float s_u[DKK];
    __shared__ float s_dp[2];

    if (tid < DKK) s_u[tid] = bonus[hh * DKK + tid];
    __syncthreads();

    float h[32];
#pragma unroll
    for (int i = 0; i < 32; i++) h[i] = 0.f;

    const size_t rb = (size_t)(b * TT) * KK + hh * DKK;
    const size_t vb = (size_t)(b * TT) * VV + hh * DVV;

    for (int t = 0; t < TT; ++t) {
        const size_t ro = rb + (size_t)t * KK;
        const size_t vo = vb + (size_t)t * VV;

        if (tid < DKK) {
            float kv_ = k[ro + tid];
            float rv_ = r[ro + tid];
            float uk_ = s_u[tid] * kv_;
            s_r[tid] = rv_;
            s_k[tid] = kv_;
            s_uk[tid] = uk_;
            s_ew[tid] = expf(w[ro + tid]);
            float dp = rv_ * uk_;
#pragma unroll
            for (int off = 16; off > 0; off >>= 1)
                dp += __shfl_xor_sync(0xffffffff, dp, off);
            if ((tid & 31) == 0) s_dp[tid >> 5] = dp;
        }
        if (tid >= 128) s_v[tid - 128] = v[vo + (tid - 128)];
        __syncthreads();

        const float vvv = s_v[vv];
        float accp = 0.f;
#pragma unroll
        for (int i = 0; i < 32; i++) {
            const int kkk = kbase + i;
            const float hv = h[i];
            accp += s_r[kkk] * hv;
            h[i] = hv * s_ew[kkk] + s_k[kkk] * vvv;
        }
        if (half == 1) s_part[vv] = accp;
        __syncthreads();
        if (half == 0) {
            const float d = s_dp[0] + s_dp[1];
            o[vo + vv] = accp + s_part[vv] + d * vvv;
        }
        // s_* for next step are only rewritten after the next __syncthreads()
    }
}

// ---------------- groupnorm + silu gate (in-place on o) ----------------
// one block = one (b,t,h) row of DV=128
__global__ __launch_bounds__(128)
void post_kernel(float* __restrict__ o, const float* __restrict__ g,
                 const float* __restrict__ gnw)
{
    const int row = blockIdx.x;
    const int vv = threadIdx.x;
    const size_t idx = (size_t)row * DVV + vv;
    float val = o[idx];
    float sq = val * val;
#pragma unroll
    for (int off = 16; off > 0; off >>= 1)
        sq += __shfl_xor_sync(0xffffffff, sq, off);
    __shared__ float sw[4];
    if ((vv & 31) == 0) sw[vv >> 5] = sq;
    __syncthreads();
    float ms = (sw[0] + sw[1] + sw[2] + sw[3]) * (1.f / 128.f);
    float gv = g[idx];
    float sig = 1.f / (1.f + expf(-gv));
    o[idx] = val * rsqrtf(ms + 1e-5f) * gnw[vv] * gv * sig;
}

// ---------------- launch ----------------
extern "C" void kernel_launch(void* const* d_in, const int* in_sizes, int n_in,
                              void* d_out, int out_size)
{
    const float* x        = (const float*)d_in[0];
    const float* W_r      = (const float*)d_in[1];
    const float* mu_r     = (const float*)d_in[2];
    const float* W_k      = (const float*)d_in[3];
    const float* mu_k     = (const float*)d_in[4];
    const float* W_v      = (const float*)d_in[5];
    const float* mu_v     = (const float*)d_in[6];
    const float* W_g      = (const float*)d_in[7];
    const float* mu_g     = (const float*)d_in[8];
    const float* dd_mu    = (const float*)d_in[9];
    const float* dd_W1    = (const float*)d_in[10];
    const float* dd_W2    = (const float*)d_in[11];
    const float* dd_lamda = (const float*)d_in[12];
    const float* w_W1     = (const float*)d_in[13];
    const float* w_W2     = (const float*)d_in[14];
    const float* w_lamda  = (const float*)d_in[15];
    const float* bonus    = (const float*)d_in[16];
    const float* W_o      = (const float*)d_in[17];
    const float* g_norm_w = (const float*)d_in[18];
    float* out = (float*)d_out;

    float *rP, *kP, *vP, *gP, *wP, *xwP, *h1P, *h2P, *oP;
    cudaGetSymbolAddress((void**)&rP,  g_r);
    cudaGetSymbolAddress((void**)&kP,  g_k);
    cudaGetSymbolAddress((void**)&vP,  g_v);
    cudaGetSymbolAddress((void**)&gP,  g_g);
    cudaGetSymbolAddress((void**)&wP,  g_w);
    cudaGetSymbolAddress((void**)&xwP, g_xw);
    cudaGetSymbolAddress((void**)&h1P, g_h1);
    cudaGetSymbolAddress((void**)&h2P, g_h2);
    cudaGetSymbolAddress((void**)&oP,  g_o);

    const dim3 blk(256);
    const dim3 gridMy(1, MM / GBM);                 // N=32
    const dim3 gridK(KK / GBN, MM / GBM);           // N=1024
    const dim3 gridV(VV / GBN, MM / GBM);           // N=2048

    // w-path (LoRA chains)
    gemm_kernel<1, 1><<<gridMy, blk>>>(x,   dd_W1, h1P, MM, 32,  DD, dd_mu, nullptr,  nullptr);
    gemm_kernel<0, 2><<<gridK,  blk>>>(h1P, dd_W2, xwP, MM, DD,  32, nullptr, dd_lamda, x);
    gemm_kernel<0, 1><<<gridMy, blk>>>(xwP, w_W1,  h2P, MM, 32,  DD, nullptr, nullptr,  nullptr);
    gemm_kernel<0, 3><<<gridK,  blk>>>(h2P, w_W2,  wP,  MM, KK,  32, nullptr, w_lamda,  nullptr);

    // projections (token-shift modulation fused into A loader)
    gemm_kernel<1, 0><<<gridK, blk>>>(x, W_r, rP, MM, KK, DD, mu_r, nullptr, nullptr);
    gemm_kernel<1, 0><<<gridK, blk>>>(x, W_k, kP, MM, KK, DD, mu_k, nullptr, nullptr);
    gemm_kernel<1, 0><<<gridV, blk>>>(x, W_v, vP, MM, VV, DD, mu_v, nullptr, nullptr);
    gemm_kernel<1, 0><<<gridV, blk>>>(x, W_g, gP, MM, VV, DD, mu_g, nullptr, nullptr);

    // recurrence
    scan_kernel<<<BB * HH, 256>>>(rP, kP, vP, wP, bonus, oP);

    // groupnorm + silu gate (in place)
    post_kernel<<<MM * HH, 128>>>(oP, gP, g_norm_w);

    // output projection
    gemm_kernel<0, 0><<<gridK, blk>>>(oP, W_o, out, MM, DD, VV, nullptr, nullptr, nullptr);
}